// round 4
// baseline (speedup 1.0000x reference)
#include <cuda_runtime.h>
#include <math.h>

#define NN 4096
#define AA 512
#define CC 100
#define MCH 8

// Round fp32 -> tf32 (round-to-nearest-away, matching tensor-core cvt.rna)
__device__ __forceinline__ float tf32r(float x) {
    unsigned u;
    asm("cvt.rna.tf32.f32 %0, %1;" : "=r"(u) : "f"(x));
    return __uint_as_float(u);
}

// ---------------- scratch (device globals; no allocation) ----------------
__device__ float g_counts[CC];
__device__ float g_w[CC];
__device__ int   g_off[CC + 1];
__device__ int   g_idx[NN];
__device__ float g_ave[CC * AA];
__device__ float g_rowloss[NN];

// ---------------- K1: histogram + offsets + mixing weights ----------------
__global__ void k_hist(const int* __restrict__ labels,
                       const float* __restrict__ amount) {
    __shared__ int sc[CC];
    int tid = threadIdx.x;
    for (int i = tid; i < CC; i += blockDim.x) sc[i] = 0;
    __syncthreads();
    for (int n = tid; n < NN; n += blockDim.x)
        atomicAdd(&sc[labels[n]], 1);
    __syncthreads();
    if (tid == 0) {
        int off = 0;
        for (int c = 0; c < CC; c++) { g_off[c] = off; off += sc[c]; }
        g_off[CC] = off;
    }
    if (tid < CC) {
        float cnt = (float)sc[tid];
        g_counts[tid] = cnt;
        float den = cnt + amount[tid];
        g_w[tid] = (den > 0.f) ? (cnt / den) : 0.f;
    }
}

// ---------------- K2: stable member-list build (warp per class) ----------------
__global__ void k_build(const int* __restrict__ labels) {
    int w = (blockIdx.x * blockDim.x + threadIdx.x) >> 5;
    int lane = threadIdx.x & 31;
    if (w >= CC) return;
    int base = g_off[w];
    for (int n0 = 0; n0 < NN; n0 += 32) {
        int n = n0 + lane;
        int match = (labels[n] == w);
        unsigned mask = __ballot_sync(0xffffffffu, (unsigned)match);
        if (match) {
            int r = __popc(mask & ((1u << lane) - 1u));
            g_idx[base + r] = n;
        }
        base += __popc(mask);
    }
}

// ---------------- K3: per-class mean (TF32-rounded inputs, fp32 accumulate) ----------------
__global__ void k_ave(const float* __restrict__ f) {
    int c = blockIdx.x;
    int tid = threadIdx.x;  // 256 threads, each handles 2 features
    int base = g_off[c];
    int cnt = g_off[c + 1] - base;
    float s0 = 0.f, s1 = 0.f;
    for (int m = 0; m < cnt; m++) {
        int n = g_idx[base + m];
        s0 += tf32r(f[n * AA + tid]);
        s1 += tf32r(f[n * AA + 256 + tid]);
    }
    float cs = (cnt > 0) ? (float)cnt : 1.f;
    g_ave[c * AA + tid] = s0 / cs;
    g_ave[c * AA + 256 + tid] = s1 / cs;
}

// ---------------- K4: per-class scatter GEMM (TF32-emulated) + fused EMA epilogue ---------
__global__ __launch_bounds__(256, 2)
void k_cov(const float* __restrict__ f,
           const float* __restrict__ cov_old,
           const float* __restrict__ ave_old,
           float* __restrict__ out_cov) {
    int c  = blockIdx.z;
    int bi = blockIdx.y;
    int bj = blockIdx.x;
    int tid = threadIdx.x;

    __shared__ float xs[MCH][128];
    __shared__ float ys[MCH][128];
    __shared__ float avx[128];
    __shared__ float avy[128];

    if (tid < 128) avx[tid]       = g_ave[c * AA + bi * 128 + tid];
    else           avy[tid - 128] = g_ave[c * AA + bj * 128 + (tid - 128)];

    int base = g_off[c];
    int cnt  = g_off[c + 1] - base;

    float acc[8][8];
#pragma unroll
    for (int i = 0; i < 8; i++)
#pragma unroll
        for (int j = 0; j < 8; j++) acc[i][j] = 0.f;

    int ti = tid >> 4;
    int tj = tid & 15;

    for (int m0 = 0; m0 < cnt; m0 += MCH) {
        int mm = min(MCH, cnt - m0);
        __syncthreads();
        // centered value rounded to TF32 BEFORE the product, like the reference einsum
        if (tid < 128) {
            for (int m = 0; m < mm; m++) {
                int n = g_idx[base + m0 + m];
                xs[m][tid] = tf32r(f[n * AA + bi * 128 + tid] - avx[tid]);
            }
        } else {
            int t = tid - 128;
            for (int m = 0; m < mm; m++) {
                int n = g_idx[base + m0 + m];
                ys[m][t] = tf32r(f[n * AA + bj * 128 + t] - avy[t]);
            }
        }
        __syncthreads();
        for (int m = 0; m < mm; m++) {
            float4 xa = *(const float4*)&xs[m][ti * 8];
            float4 xb = *(const float4*)&xs[m][ti * 8 + 4];
            float4 ya = *(const float4*)&ys[m][tj * 8];
            float4 yb = *(const float4*)&ys[m][tj * 8 + 4];
            float xv[8] = {xa.x, xa.y, xa.z, xa.w, xb.x, xb.y, xb.z, xb.w};
            float yv[8] = {ya.x, ya.y, ya.z, ya.w, yb.x, yb.y, yb.z, yb.w};
#pragma unroll
            for (int i = 0; i < 8; i++)
#pragma unroll
                for (int j = 0; j < 8; j++)
                    acc[i][j] += xv[i] * yv[j];
        }
    }

    // ---- fused epilogue: new_cov = cov_old*(1-w) + (acc/cnt_safe)*w + w(1-w)*diff_i*diff_j
    float wv  = g_w[c];
    float om  = 1.f - wv;
    float cs  = (cnt > 0) ? (float)cnt : 1.f;
    float inv = wv / cs;
    float coef = wv * om;

    float da[8], db[8];
#pragma unroll
    for (int i = 0; i < 8; i++) {
        int r = bi * 128 + ti * 8 + i;
        da[i] = ave_old[c * AA + r] - avx[ti * 8 + i];
    }
#pragma unroll
    for (int j = 0; j < 8; j++) {
        int col = bj * 128 + tj * 8 + j;
        db[j] = ave_old[c * AA + col] - avy[tj * 8 + j];
    }

    size_t cb = (size_t)c * AA * AA;
#pragma unroll
    for (int i = 0; i < 8; i++) {
        size_t ro = cb + (size_t)(bi * 128 + ti * 8 + i) * AA + bj * 128 + tj * 8;
#pragma unroll
        for (int j = 0; j < 8; j++) {
            out_cov[ro + j] = cov_old[ro + j] * om + acc[i][j] * inv
                              + coef * da[i] * db[j];
        }
    }
}

// ---------------- K5: new_ave, new_amount ----------------
__global__ void k_avout(const float* __restrict__ ave_old,
                        const float* __restrict__ amount_old,
                        float* __restrict__ out_ave,
                        float* __restrict__ out_amt) {
    int i = blockIdx.x * blockDim.x + threadIdx.x;
    if (i < CC * AA) {
        int c = i / AA;
        float wv = g_w[c];
        out_ave[i] = ave_old[i] * (1.f - wv) + g_ave[i] * wv;
    }
    if (i < CC) out_amt[i] = amount_old[i] + g_counts[i];
}

// ---------------- K6: per-row NLL (warp per row) ----------------
__global__ void k_loss(const float* __restrict__ ys,
                       const int* __restrict__ labels) {
    int row  = (blockIdx.x * blockDim.x + threadIdx.x) >> 5;
    int lane = threadIdx.x & 31;
    if (row >= NN) return;
    const float* r = ys + (size_t)row * CC;
    float v0 = r[lane];
    float v1 = r[lane + 32];
    float v2 = r[lane + 64];
    float v3 = (lane < 4) ? r[lane + 96] : -INFINITY;
    float mx = fmaxf(fmaxf(v0, v1), fmaxf(v2, v3));
#pragma unroll
    for (int o = 16; o > 0; o >>= 1)
        mx = fmaxf(mx, __shfl_xor_sync(0xffffffffu, mx, o));
    float s = expf(v0 - mx) + expf(v1 - mx) + expf(v2 - mx)
            + ((lane < 4) ? expf(v3 - mx) : 0.f);
#pragma unroll
    for (int o = 16; o > 0; o >>= 1)
        s += __shfl_xor_sync(0xffffffffu, s, o);
    if (lane == 0) {
        int lab = labels[row];
        g_rowloss[row] = (mx + logf(s)) - r[lab];
    }
}

// ---------------- K7: deterministic tree reduce ----------------
__global__ void k_red(float* __restrict__ out_loss) {
    __shared__ float s[1024];
    int t = threadIdx.x;
    s[t] = g_rowloss[t] + g_rowloss[t + 1024] + g_rowloss[t + 2048] + g_rowloss[t + 3072];
    __syncthreads();
    for (int st = 512; st > 0; st >>= 1) {
        if (t < st) s[t] += s[t + st];
        __syncthreads();
    }
    if (t == 0) out_loss[0] = s[0] / (float)NN;
}

// ---------------- launcher ----------------
extern "C" void kernel_launch(void* const* d_in, const int* in_sizes, int n_in,
                              void* d_out, int out_size) {
    const float* features = (const float*)d_in[0];
    const float* y_s      = (const float*)d_in[1];
    const float* cov_old  = (const float*)d_in[2];
    const float* ave_old  = (const float*)d_in[3];
    const float* amount   = (const float*)d_in[4];
    const int*   labels   = (const int*)d_in[5];

    float* out      = (float*)d_out;
    float* out_loss = out;
    float* out_cov  = out + 1;
    float* out_ave  = out + 1 + (size_t)CC * AA * AA;
    float* out_amt  = out_ave + (size_t)CC * AA;

    k_hist<<<1, 256>>>(labels, amount);
    k_build<<<(CC * 32 + 255) / 256, 256>>>(labels);
    k_ave<<<CC, 256>>>(features);
    dim3 gcov(4, 4, CC);
    k_cov<<<gcov, 256>>>(features, cov_old, ave_old, out_cov);
    k_avout<<<(CC * AA + 255) / 256, 256>>>(ave_old, amount, out_ave, out_amt);
    k_loss<<<NN / 8, 256>>>(y_s, labels);
    k_red<<<1, 1024>>>(out_loss);
}

// round 6
// speedup vs baseline: 1.1817x; 1.1817x over previous
#include <cuda_runtime.h>
#include <math.h>

#define NN 4096
#define AA 512
#define CC 100
#define PADT 5600   // >= NN + 15*CC

// Round fp32 -> tf32 (round-to-nearest-away), matching passing-round numerics
__device__ __forceinline__ float tf32r(float x) {
    unsigned u;
    asm("cvt.rna.tf32.f32 %0, %1;" : "=r"(u) : "f"(x));
    return __uint_as_float(u);
}

__device__ __forceinline__ unsigned long long pk2(float lo, float hi) {
    unsigned long long r;
    asm("mov.b64 %0, {%1,%2};" : "=l"(r) : "f"(lo), "f"(hi));
    return r;
}
__device__ __forceinline__ void upk2(unsigned long long v, float& lo, float& hi) {
    asm("mov.b64 {%0,%1}, %2;" : "=f"(lo), "=f"(hi) : "l"(v));
}
__device__ __forceinline__ void fma2(unsigned long long& d, unsigned long long a,
                                     unsigned long long b) {
    asm("fma.rn.f32x2 %0, %1, %2, %0;" : "+l"(d) : "l"(a), "l"(b));
}
__device__ __forceinline__ void cpa16(void* smem, const void* gmem) {
    unsigned s = (unsigned)__cvta_generic_to_shared(smem);
    asm volatile("cp.async.cg.shared.global [%0], [%1], 16;" :: "r"(s), "l"(gmem));
}
#define CPCOMMIT() asm volatile("cp.async.commit_group;")
#define CPWAIT1()  asm volatile("cp.async.wait_group 1;" ::: "memory")
#define CPWAIT0()  asm volatile("cp.async.wait_group 0;" ::: "memory")

// ---------------- scratch ----------------
__device__ float g_counts[CC];
__device__ float g_w[CC];
__device__ int   g_off[CC + 1];
__device__ int   g_offp[CC + 1];
__device__ int   g_idx[NN];
__device__ float g_ave[CC * AA];
__device__ float g_rowloss[NN];
__device__ float4 g_cent[PADT * AA / 4];   // class-sorted, padded, 16B-aligned

// ---------------- K1: histogram + offsets (+padded) + weights ----------------
__global__ void k_hist(const int* __restrict__ labels,
                       const float* __restrict__ amount) {
    __shared__ int sc[CC];
    int tid = threadIdx.x;
    for (int i = tid; i < CC; i += blockDim.x) sc[i] = 0;
    __syncthreads();
    for (int n = tid; n < NN; n += blockDim.x)
        atomicAdd(&sc[labels[n]], 1);
    __syncthreads();
    if (tid == 0) {
        int off = 0, offp = 0;
        for (int c = 0; c < CC; c++) {
            g_off[c] = off;  g_offp[c] = offp;
            off += sc[c];    offp += (sc[c] + 15) & ~15;
        }
        g_off[CC] = off; g_offp[CC] = offp;
    }
    if (tid < CC) {
        float cnt = (float)sc[tid];
        g_counts[tid] = cnt;
        float den = cnt + amount[tid];
        g_w[tid] = (den > 0.f) ? (cnt / den) : 0.f;
    }
}

// ---------------- K2: stable member lists (warp per class) ----------------
__global__ void k_build(const int* __restrict__ labels) {
    int w = (blockIdx.x * blockDim.x + threadIdx.x) >> 5;
    int lane = threadIdx.x & 31;
    if (w >= CC) return;
    int base = g_off[w];
    for (int n0 = 0; n0 < NN; n0 += 32) {
        int n = n0 + lane;
        int match = (labels[n] == w);
        unsigned mask = __ballot_sync(0xffffffffu, (unsigned)match);
        if (match) {
            int r = __popc(mask & ((1u << lane) - 1u));
            g_idx[base + r] = n;
        }
        base += __popc(mask);
    }
}

// ---------------- K3: per-class mean (TF32-rounded inputs, fp32 acc) ----------------
__global__ void k_ave(const float* __restrict__ f) {
    int c = blockIdx.x;
    int tid = threadIdx.x;
    int base = g_off[c];
    int cnt = g_off[c + 1] - base;
    float s0 = 0.f, s1 = 0.f;
    for (int m = 0; m < cnt; m++) {
        int n = g_idx[base + m];
        s0 += tf32r(f[n * AA + tid]);
        s1 += tf32r(f[n * AA + 256 + tid]);
    }
    float cs = (cnt > 0) ? (float)cnt : 1.f;
    g_ave[c * AA + tid] = s0 / cs;
    g_ave[c * AA + 256 + tid] = s1 / cs;
}

// ---------------- K3b: centered, tf32-rounded, class-sorted, zero-padded ----------------
__global__ void k_center(const float* __restrict__ f) {
    __shared__ int s_c;
    int b = blockIdx.x;
    if (threadIdx.x == 0) {
        if (b >= g_offp[CC]) s_c = -1;
        else {
            int lo = 0, hi = CC - 1;
            while (lo < hi) {
                int mid = (lo + hi + 1) >> 1;
                if (g_offp[mid] <= b) lo = mid; else hi = mid - 1;
            }
            s_c = lo;
        }
    }
    __syncthreads();
    int c = s_c;
    if (c < 0) return;
    int m = b - g_offp[c];
    int cnt = g_off[c + 1] - g_off[c];
    float* dst = (float*)g_cent + (size_t)b * AA;
    int t = threadIdx.x;   // 128 threads x 4 cols
    if (m < cnt) {
        int n = g_idx[g_off[c] + m];
        const float* src = f + (size_t)n * AA;
#pragma unroll
        for (int k = 0; k < 4; k++) {
            int col = t + k * 128;
            dst[col] = tf32r(src[col] - g_ave[c * AA + col]);
        }
    } else {
#pragma unroll
        for (int k = 0; k < 4; k++) dst[t + k * 128] = 0.f;
    }
}

// ---------------- K4: streaming scatter GEMM (FFMA2 + cp.async dbl-buf) ----------------
__global__ __launch_bounds__(256, 2)
void k_cov(const float* __restrict__ cov_old,
           const float* __restrict__ ave_old,
           float* __restrict__ out_cov) {
    int c  = blockIdx.z;
    int bi = blockIdx.y;
    int bj = blockIdx.x;
    int tid = threadIdx.x;

    __shared__ float4 xs[2][512];   // 16 rows x 128 floats
    __shared__ float4 ys[2][512];

    int base = g_offp[c];
    int cntp = g_offp[c + 1] - base;   // multiple of 16
    int cnt  = g_off[c + 1] - g_off[c];

    unsigned long long acc[8][4];
#pragma unroll
    for (int i = 0; i < 8; i++)
#pragma unroll
        for (int j = 0; j < 4; j++) acc[i][j] = 0ull;

    int ti = tid >> 4;
    int tj = tid & 15;

    const float* centf = (const float*)g_cent;

    // stage chunk [m0, m0+16) into buffer `buf`
    auto stage = [&](int buf, int m0) {
#pragma unroll
        for (int r = 0; r < 2; r++) {
            int e = tid + r * 256;          // 0..511
            int row = e >> 5, q = e & 31;
            const float* sx = centf + (size_t)(base + m0 + row) * AA + bi * 128 + q * 4;
            const float* sy = centf + (size_t)(base + m0 + row) * AA + bj * 128 + q * 4;
            cpa16(&xs[buf][e], sx);
            cpa16(&ys[buf][e], sy);
        }
    };

    if (cntp > 0) {
        stage(0, 0); CPCOMMIT();
        for (int m0 = 0; m0 < cntp; m0 += 16) {
            int cur = (m0 >> 4) & 1;
            if (m0 + 16 < cntp) { stage(cur ^ 1, m0 + 16); CPCOMMIT(); CPWAIT1(); }
            else                { CPWAIT0(); }
            __syncthreads();
#pragma unroll 4
            for (int m = 0; m < 16; m++) {
                float4 xa = xs[cur][m * 32 + ti * 2];
                float4 xb = xs[cur][m * 32 + ti * 2 + 1];
                float4 ya = ys[cur][m * 32 + tj * 2];
                float4 yb = ys[cur][m * 32 + tj * 2 + 1];
                unsigned long long xx[8], yy[4];
                xx[0] = pk2(xa.x, xa.x); xx[1] = pk2(xa.y, xa.y);
                xx[2] = pk2(xa.z, xa.z); xx[3] = pk2(xa.w, xa.w);
                xx[4] = pk2(xb.x, xb.x); xx[5] = pk2(xb.y, xb.y);
                xx[6] = pk2(xb.z, xb.z); xx[7] = pk2(xb.w, xb.w);
                yy[0] = pk2(ya.x, ya.y); yy[1] = pk2(ya.z, ya.w);
                yy[2] = pk2(yb.x, yb.y); yy[3] = pk2(yb.z, yb.w);
#pragma unroll
                for (int i = 0; i < 8; i++)
#pragma unroll
                    for (int j = 0; j < 4; j++)
                        fma2(acc[i][j], xx[i], yy[j]);
            }
            __syncthreads();
        }
    }

    // ---- fused epilogue (vector loads from aligned cov_old, SCALAR stores: out_cov
    //      is d_out+1 float => only 4-byte aligned) ----
    float wv  = g_w[c];
    float om  = 1.f - wv;
    float cs  = (cnt > 0) ? (float)cnt : 1.f;
    float inv = wv / cs;
    float coef = wv * om;

    float da[8], db[8];
#pragma unroll
    for (int i = 0; i < 8; i++) {
        int r = bi * 128 + ti * 8 + i;
        da[i] = ave_old[c * AA + r] - g_ave[c * AA + r];
    }
#pragma unroll
    for (int j = 0; j < 8; j++) {
        int col = bj * 128 + tj * 8 + j;
        db[j] = ave_old[c * AA + col] - g_ave[c * AA + col];
    }

    size_t cb = (size_t)c * AA * AA;
#pragma unroll
    for (int i = 0; i < 8; i++) {
        size_t ro = cb + (size_t)(bi * 128 + ti * 8 + i) * AA + bj * 128 + tj * 8;
        float4 c0 = *(const float4*)(cov_old + ro);
        float4 c1 = *(const float4*)(cov_old + ro + 4);
        float a0, a1, a2, a3, a4, a5, a6, a7;
        upk2(acc[i][0], a0, a1); upk2(acc[i][1], a2, a3);
        upk2(acc[i][2], a4, a5); upk2(acc[i][3], a6, a7);
        float cd = coef * da[i];
        out_cov[ro + 0] = c0.x * om + a0 * inv + cd * db[0];
        out_cov[ro + 1] = c0.y * om + a1 * inv + cd * db[1];
        out_cov[ro + 2] = c0.z * om + a2 * inv + cd * db[2];
        out_cov[ro + 3] = c0.w * om + a3 * inv + cd * db[3];
        out_cov[ro + 4] = c1.x * om + a4 * inv + cd * db[4];
        out_cov[ro + 5] = c1.y * om + a5 * inv + cd * db[5];
        out_cov[ro + 6] = c1.z * om + a6 * inv + cd * db[6];
        out_cov[ro + 7] = c1.w * om + a7 * inv + cd * db[7];
    }
}

// ---------------- K5: new_ave, new_amount ----------------
__global__ void k_avout(const float* __restrict__ ave_old,
                        const float* __restrict__ amount_old,
                        float* __restrict__ out_ave,
                        float* __restrict__ out_amt) {
    int i = blockIdx.x * blockDim.x + threadIdx.x;
    if (i < CC * AA) {
        int c = i / AA;
        float wv = g_w[c];
        out_ave[i] = ave_old[i] * (1.f - wv) + g_ave[i] * wv;
    }
    if (i < CC) out_amt[i] = amount_old[i] + g_counts[i];
}

// ---------------- K6: per-row NLL (warp per row) ----------------
__global__ void k_loss(const float* __restrict__ ys,
                       const int* __restrict__ labels) {
    int row  = (blockIdx.x * blockDim.x + threadIdx.x) >> 5;
    int lane = threadIdx.x & 31;
    if (row >= NN) return;
    const float* r = ys + (size_t)row * CC;
    float v0 = r[lane];
    float v1 = r[lane + 32];
    float v2 = r[lane + 64];
    float v3 = (lane < 4) ? r[lane + 96] : -INFINITY;
    float mx = fmaxf(fmaxf(v0, v1), fmaxf(v2, v3));
#pragma unroll
    for (int o = 16; o > 0; o >>= 1)
        mx = fmaxf(mx, __shfl_xor_sync(0xffffffffu, mx, o));
    float s = expf(v0 - mx) + expf(v1 - mx) + expf(v2 - mx)
            + ((lane < 4) ? expf(v3 - mx) : 0.f);
#pragma unroll
    for (int o = 16; o > 0; o >>= 1)
        s += __shfl_xor_sync(0xffffffffu, s, o);
    if (lane == 0) {
        int lab = labels[row];
        g_rowloss[row] = (mx + logf(s)) - r[lab];
    }
}

// ---------------- K7: deterministic tree reduce ----------------
__global__ void k_red(float* __restrict__ out_loss) {
    __shared__ float s[1024];
    int t = threadIdx.x;
    s[t] = g_rowloss[t] + g_rowloss[t + 1024] + g_rowloss[t + 2048] + g_rowloss[t + 3072];
    __syncthreads();
    for (int st = 512; st > 0; st >>= 1) {
        if (t < st) s[t] += s[t + st];
        __syncthreads();
    }
    if (t == 0) out_loss[0] = s[0] / (float)NN;
}

// ---------------- launcher ----------------
extern "C" void kernel_launch(void* const* d_in, const int* in_sizes, int n_in,
                              void* d_out, int out_size) {
    const float* features = (const float*)d_in[0];
    const float* y_s      = (const float*)d_in[1];
    const float* cov_old  = (const float*)d_in[2];
    const float* ave_old  = (const float*)d_in[3];
    const float* amount   = (const float*)d_in[4];
    const int*   labels   = (const int*)d_in[5];

    float* out      = (float*)d_out;
    float* out_loss = out;
    float* out_cov  = out + 1;
    float* out_ave  = out + 1 + (size_t)CC * AA * AA;
    float* out_amt  = out_ave + (size_t)CC * AA;

    k_hist<<<1, 256>>>(labels, amount);
    k_build<<<(CC * 32 + 255) / 256, 256>>>(labels);
    k_ave<<<CC, 256>>>(features);
    k_center<<<PADT, 128>>>(features);
    dim3 gcov(4, 4, CC);
    k_cov<<<gcov, 256>>>(cov_old, ave_old, out_cov);
    k_avout<<<(CC * AA + 255) / 256, 256>>>(ave_old, amount, out_ave, out_amt);
    k_loss<<<NN / 8, 256>>>(y_s, labels);
    k_red<<<1, 1024>>>(out_loss);
}

// round 8
// speedup vs baseline: 1.5566x; 1.3172x over previous
#include <cuda_runtime.h>
#include <math.h>

#define NN 4096
#define AA 512
#define CC 100
#define PADT 7296   // >= NN + 31*CC, multiple of 32

// Round fp32 -> tf32 (round-to-nearest-away)
__device__ __forceinline__ float tf32r(float x) {
    unsigned u;
    asm("cvt.rna.tf32.f32 %0, %1;" : "=r"(u) : "f"(x));
    return __uint_as_float(u);
}
__device__ __forceinline__ void cpa16(unsigned s, const void* gmem) {
    asm volatile("cp.async.cg.shared.global [%0], [%1], 16;" :: "r"(s), "l"(gmem));
}
#define CPCOMMIT() asm volatile("cp.async.commit_group;")
#define CPWAIT0()  asm volatile("cp.async.wait_group 0;" ::: "memory")

// ---------------- scratch ----------------
__device__ float g_counts[CC];
__device__ float g_w[CC];
__device__ int   g_off[CC + 1];
__device__ int   g_offp[CC + 1];
__device__ int   g_idx[NN];
__device__ float g_ave[CC * AA];
__device__ float g_rowloss[NN];
__device__ float g_centT[(size_t)AA * PADT];  // feature-major (K = member dim)

// ---------------- K1: histogram + offsets (padded to 32) + weights ----------------
__global__ void k_hist(const int* __restrict__ labels,
                       const float* __restrict__ amount) {
    __shared__ int sc[CC];
    int tid = threadIdx.x;
    for (int i = tid; i < CC; i += blockDim.x) sc[i] = 0;
    __syncthreads();
    for (int n = tid; n < NN; n += blockDim.x)
        atomicAdd(&sc[labels[n]], 1);
    __syncthreads();
    if (tid == 0) {
        int off = 0, offp = 0;
        for (int c = 0; c < CC; c++) {
            g_off[c] = off;  g_offp[c] = offp;
            off += sc[c];    offp += (sc[c] + 31) & ~31;
        }
        g_off[CC] = off; g_offp[CC] = offp;
    }
    if (tid < CC) {
        float cnt = (float)sc[tid];
        g_counts[tid] = cnt;
        float den = cnt + amount[tid];
        g_w[tid] = (den > 0.f) ? (cnt / den) : 0.f;
    }
}

// ---------------- K2: stable member lists (warp per class) ----------------
__global__ void k_build(const int* __restrict__ labels) {
    int w = (blockIdx.x * blockDim.x + threadIdx.x) >> 5;
    int lane = threadIdx.x & 31;
    if (w >= CC) return;
    int base = g_off[w];
    for (int n0 = 0; n0 < NN; n0 += 32) {
        int n = n0 + lane;
        int match = (labels[n] == w);
        unsigned mask = __ballot_sync(0xffffffffu, (unsigned)match);
        if (match) {
            int r = __popc(mask & ((1u << lane) - 1u));
            g_idx[base + r] = n;
        }
        base += __popc(mask);
    }
}

// ---------------- K3: per-class mean (TF32-rounded inputs, fp32 acc) ----------------
__global__ void k_ave(const float* __restrict__ f) {
    int c = blockIdx.x;
    int tid = threadIdx.x;
    int base = g_off[c];
    int cnt = g_off[c + 1] - base;
    float s0 = 0.f, s1 = 0.f;
    for (int m = 0; m < cnt; m++) {
        int n = g_idx[base + m];
        s0 += tf32r(f[n * AA + tid]);
        s1 += tf32r(f[n * AA + 256 + tid]);
    }
    float cs = (cnt > 0) ? (float)cnt : 1.f;
    g_ave[c * AA + tid] = s0 / cs;
    g_ave[c * AA + 256 + tid] = s1 / cs;
}

// ---------------- K3b: centered tf32, transposed to feature-major ----------------
__global__ void k_centerT(const float* __restrict__ f) {
    __shared__ float tile[16][512];
    __shared__ int s_c;
    int b = blockIdx.x;
    int row0 = b * 16;
    if (threadIdx.x == 0) {
        if (row0 >= g_offp[CC]) s_c = -1;
        else {
            int lo = 0, hi = CC - 1;
            while (lo < hi) {
                int mid = (lo + hi + 1) >> 1;
                if (g_offp[mid] <= row0) lo = mid; else hi = mid - 1;
            }
            s_c = lo;
        }
    }
    __syncthreads();
    int c = s_c;
    if (c < 0) return;
    int cnt = g_off[c + 1] - g_off[c];
    int t = threadIdx.x;  // 256
    for (int e = t; e < 16 * 128; e += 256) {
        int m = e >> 7;
        int q = e & 127;
        int mloc = row0 + m - g_offp[c];
        float4 v = make_float4(0.f, 0.f, 0.f, 0.f);
        if (mloc < cnt) {
            int n = g_idx[g_off[c] + mloc];
            float4 src = *(const float4*)(f + (size_t)n * AA + q * 4);
            const float* av = g_ave + c * AA + q * 4;
            v.x = tf32r(src.x - av[0]);
            v.y = tf32r(src.y - av[1]);
            v.z = tf32r(src.z - av[2]);
            v.w = tf32r(src.w - av[3]);
        }
        *(float4*)&tile[m][q * 4] = v;
    }
    __syncthreads();
    for (int e = t; e < 512 * 4; e += 256) {
        int a = e >> 2;
        int g = e & 3;
        float4 w;
        w.x = tile[g * 4 + 0][a];
        w.y = tile[g * 4 + 1][a];
        w.z = tile[g * 4 + 2][a];
        w.w = tile[g * 4 + 3][a];
        *(float4*)(g_centT + (size_t)a * PADT + row0 + g * 4) = w;
    }
}

// ---------------- K4: tf32 mma.sync scatter GEMM + fused EMA epilogue ----------------
#define SROW 36   // smem row stride (floats); bank = (4g+tig+const)&31 -> conflict-free

__global__ __launch_bounds__(256)
void k_cov(const float* __restrict__ cov_old,
           const float* __restrict__ ave_old,
           float* __restrict__ out_cov) {
    __shared__ float sA[128 * SROW];
    __shared__ float sB[128 * SROW];
    __shared__ float s_db[128];
    __shared__ float s_cd[128];

    int c  = blockIdx.z;
    int bi = blockIdx.y;
    int bj = blockIdx.x;
    int tid = threadIdx.x;
    int w = tid >> 5, lane = tid & 31;
    int wm = w >> 2, wn = w & 3;        // warp tile origin (wm*64, wn*32)
    int g = lane >> 2, tig = lane & 3;

    unsigned sA_u = (unsigned)__cvta_generic_to_shared(sA);
    unsigned sB_u = (unsigned)__cvta_generic_to_shared(sB);

    int base = g_offp[c];
    int cntp = g_offp[c + 1] - base;    // multiple of 32
    int cnt  = g_off[c + 1] - g_off[c];

    if (tid < 128) {
        int colg = c * AA + bj * 128 + tid;
        s_db[tid] = ave_old[colg] - g_ave[colg];
        int rowg = c * AA + bi * 128 + tid;
        float wv = g_w[c];
        s_cd[tid] = (wv * (1.f - wv)) * (ave_old[rowg] - g_ave[rowg]);
    }

    float acc[4][4][4];
#pragma unroll
    for (int mi = 0; mi < 4; mi++)
#pragma unroll
        for (int ni = 0; ni < 4; ni++)
#pragma unroll
            for (int q = 0; q < 4; q++) acc[mi][ni][q] = 0.f;

    for (int k0 = 0; k0 < cntp; k0 += 32) {
        // stage A,B tiles: 128 rows x 32 floats, row stride SROW (144B, 16B-aligned)
        for (int e = tid; e < 1024; e += 256) {
            int r = e >> 3, q = e & 7;
            unsigned dst = (unsigned)(r * SROW * 4 + q * 16);
            const float* srcA = g_centT + (size_t)(bi * 128 + r) * PADT + base + k0 + q * 4;
            const float* srcB = g_centT + (size_t)(bj * 128 + r) * PADT + base + k0 + q * 4;
            cpa16(sA_u + dst, srcA);
            cpa16(sB_u + dst, srcB);
        }
        CPCOMMIT(); CPWAIT0();
        __syncthreads();

#pragma unroll
        for (int ks = 0; ks < 4; ks++) {
            int kk = ks * 8;
            unsigned a[4][4], b[4][2];
#pragma unroll
            for (int mi = 0; mi < 4; mi++) {
                int r0 = wm * 64 + mi * 16;
                a[mi][0] = __float_as_uint(sA[(r0 + g)     * SROW + kk + tig]);
                a[mi][1] = __float_as_uint(sA[(r0 + g + 8) * SROW + kk + tig]);
                a[mi][2] = __float_as_uint(sA[(r0 + g)     * SROW + kk + tig + 4]);
                a[mi][3] = __float_as_uint(sA[(r0 + g + 8) * SROW + kk + tig + 4]);
            }
#pragma unroll
            for (int ni = 0; ni < 4; ni++) {
                int rn = wn * 32 + ni * 8;
                b[ni][0] = __float_as_uint(sB[(rn + g) * SROW + kk + tig]);
                b[ni][1] = __float_as_uint(sB[(rn + g) * SROW + kk + tig + 4]);
            }
#pragma unroll
            for (int mi = 0; mi < 4; mi++)
#pragma unroll
                for (int ni = 0; ni < 4; ni++) {
                    asm volatile(
                        "mma.sync.aligned.m16n8k8.row.col.f32.tf32.tf32.f32 "
                        "{%0,%1,%2,%3}, {%4,%5,%6,%7}, {%8,%9}, {%0,%1,%2,%3};"
                        : "+f"(acc[mi][ni][0]), "+f"(acc[mi][ni][1]),
                          "+f"(acc[mi][ni][2]), "+f"(acc[mi][ni][3])
                        : "r"(a[mi][0]), "r"(a[mi][1]), "r"(a[mi][2]), "r"(a[mi][3]),
                          "r"(b[ni][0]), "r"(b[ni][1]));
                }
        }
        __syncthreads();
    }

    // ---- fused EMA epilogue straight from registers ----
    __syncthreads();
    float wv  = g_w[c];
    float om  = 1.f - wv;
    float cs  = (cnt > 0) ? (float)cnt : 1.f;
    float inv = wv / cs;
    size_t cbase = (size_t)c * AA * AA;

#pragma unroll
    for (int mi = 0; mi < 4; mi++) {
        int rl0 = wm * 64 + mi * 16 + g;        // local rows rl0, rl0+8
#pragma unroll
        for (int ni = 0; ni < 4; ni++) {
            int cl = wn * 32 + ni * 8 + tig * 2;  // local col (even)
            size_t r1 = cbase + (size_t)(bi * 128 + rl0) * AA + bj * 128 + cl;
            size_t r2 = cbase + (size_t)(bi * 128 + rl0 + 8) * AA + bj * 128 + cl;
            float2 co1 = *(const float2*)(cov_old + r1);
            float2 co2 = *(const float2*)(cov_old + r2);
            float cd1 = s_cd[rl0], cd2 = s_cd[rl0 + 8];
            float db0 = s_db[cl], db1 = s_db[cl + 1];
            out_cov[r1]     = co1.x * om + acc[mi][ni][0] * inv + cd1 * db0;
            out_cov[r1 + 1] = co1.y * om + acc[mi][ni][1] * inv + cd1 * db1;
            out_cov[r2]     = co2.x * om + acc[mi][ni][2] * inv + cd2 * db0;
            out_cov[r2 + 1] = co2.y * om + acc[mi][ni][3] * inv + cd2 * db1;
        }
    }
}

// ---------------- K5: new_ave, new_amount ----------------
__global__ void k_avout(const float* __restrict__ ave_old,
                        const float* __restrict__ amount_old,
                        float* __restrict__ out_ave,
                        float* __restrict__ out_amt) {
    int i = blockIdx.x * blockDim.x + threadIdx.x;
    if (i < CC * AA) {
        int c = i / AA;
        float wv = g_w[c];
        out_ave[i] = ave_old[i] * (1.f - wv) + g_ave[i] * wv;
    }
    if (i < CC) out_amt[i] = amount_old[i] + g_counts[i];
}

// ---------------- K6: per-row NLL (warp per row) ----------------
__global__ void k_loss(const float* __restrict__ ys,
                       const int* __restrict__ labels) {
    int row  = (blockIdx.x * blockDim.x + threadIdx.x) >> 5;
    int lane = threadIdx.x & 31;
    if (row >= NN) return;
    const float* r = ys + (size_t)row * CC;
    float v0 = r[lane];
    float v1 = r[lane + 32];
    float v2 = r[lane + 64];
    float v3 = (lane < 4) ? r[lane + 96] : -INFINITY;
    float mx = fmaxf(fmaxf(v0, v1), fmaxf(v2, v3));
#pragma unroll
    for (int o = 16; o > 0; o >>= 1)
        mx = fmaxf(mx, __shfl_xor_sync(0xffffffffu, mx, o));
    float s = expf(v0 - mx) + expf(v1 - mx) + expf(v2 - mx)
            + ((lane < 4) ? expf(v3 - mx) : 0.f);
#pragma unroll
    for (int o = 16; o > 0; o >>= 1)
        s += __shfl_xor_sync(0xffffffffu, s, o);
    if (lane == 0) {
        int lab = labels[row];
        g_rowloss[row] = (mx + logf(s)) - r[lab];
    }
}

// ---------------- K7: deterministic tree reduce ----------------
__global__ void k_red(float* __restrict__ out_loss) {
    __shared__ float s[1024];
    int t = threadIdx.x;
    s[t] = g_rowloss[t] + g_rowloss[t + 1024] + g_rowloss[t + 2048] + g_rowloss[t + 3072];
    __syncthreads();
    for (int st = 512; st > 0; st >>= 1) {
        if (t < st) s[t] += s[t + st];
        __syncthreads();
    }
    if (t == 0) out_loss[0] = s[0] / (float)NN;
}

// ---------------- launcher ----------------
extern "C" void kernel_launch(void* const* d_in, const int* in_sizes, int n_in,
                              void* d_out, int out_size) {
    const float* features = (const float*)d_in[0];
    const float* y_s      = (const float*)d_in[1];
    const float* cov_old  = (const float*)d_in[2];
    const float* ave_old  = (const float*)d_in[3];
    const float* amount   = (const float*)d_in[4];
    const int*   labels   = (const int*)d_in[5];

    float* out      = (float*)d_out;
    float* out_loss = out;
    float* out_cov  = out + 1;
    float* out_ave  = out + 1 + (size_t)CC * AA * AA;
    float* out_amt  = out_ave + (size_t)CC * AA;

    k_hist<<<1, 256>>>(labels, amount);
    k_build<<<(CC * 32 + 255) / 256, 256>>>(labels);
    k_ave<<<CC, 256>>>(features);
    k_centerT<<<PADT / 16, 256>>>(features);
    dim3 gcov(4, 4, CC);
    k_cov<<<gcov, 256>>>(cov_old, ave_old, out_cov);
    k_avout<<<(CC * AA + 255) / 256, 256>>>(ave_old, amount, out_ave, out_amt);
    k_loss<<<NN / 8, 256>>>(y_s, labels);
    k_red<<<1, 1024>>>(out_loss);
}